// round 9
// baseline (speedup 1.0000x reference)
#include <cuda_runtime.h>
#include <math.h>
#include <stdint.h>

#define T_DIM 2048
#define N_DIM 2
#define C_DIM 1024
#define H_DIM 16
#define DH 64
#define M_ROWS (T_DIM * N_DIM)   // 4096
#define WINDOW 128

#define GK 1024
#define GN 1024
#define BK 32
#define NUM_CHUNKS (GK / BK)     // 32
#define SM_STRIDE 36             // 32 + 4 pad (floats)
#define STAGE_F (128 * SM_STRIDE)            // floats per matrix tile
#define GEMM_SMEM (2 * 2 * STAGE_F * 4)      // 2 stages x (A+B) = 73728 B

// Scratch (static device allocation — allowed; cudaMalloc is not)
__device__ float g_qp[M_ROWS * C_DIM];
__device__ float g_kp[M_ROWS * C_DIM];
__device__ float g_vp[M_ROWS * C_DIM];
__device__ float g_ao[M_ROWS * C_DIM];

// ---------------------------------------------------------------------------
__device__ __forceinline__ float to_tf32(float x) {
    float y;
    asm("cvt.rna.tf32.f32 %0, %1;" : "=f"(y) : "f"(x));
    return y;
}
__device__ __forceinline__ float4 to_tf32x4(float4 v) {
    return make_float4(to_tf32(v.x), to_tf32(v.y), to_tf32(v.z), to_tf32(v.w));
}

__device__ __forceinline__ void mma_tf32(float* c, const uint32_t* a,
                                         uint32_t b0, uint32_t b1) {
    asm volatile(
        "mma.sync.aligned.m16n8k8.row.col.f32.tf32.tf32.f32 "
        "{%0,%1,%2,%3}, {%4,%5,%6,%7}, {%8,%9}, {%0,%1,%2,%3};"
        : "+f"(c[0]), "+f"(c[1]), "+f"(c[2]), "+f"(c[3])
        : "r"(a[0]), "r"(a[1]), "r"(a[2]), "r"(a[3]), "r"(b0), "r"(b1));
}

// ---------------------------------------------------------------------------
// mma.sync tf32 GEMM body: C[m][n] = sum_k A[m][k]*B[n][k] + bias[n]
// CTA tile 128x128, BK=32, 8 warps (4m x 2n), warp tile 32x64.
// ---------------------------------------------------------------------------
__device__ __forceinline__ void gemm_body(
    const float* __restrict__ A, const float* __restrict__ B,
    const float* __restrict__ bias, float* __restrict__ C, float* sm)
{
    const int tid  = threadIdx.x;
    const int wid  = tid >> 5;
    const int lane = tid & 31;
    const int g    = lane >> 2;
    const int t    = lane & 3;
    const int warpM = (wid & 3) * 32;
    const int warpN = (wid >> 2) * 64;
    const int m0 = blockIdx.y * 128;
    const int n0 = blockIdx.x * 128;

    const int lr  = tid >> 3;
    const int lc4 = (tid & 7) * 4;

    float acc[2][8][4] = {};

    {
        float* As = sm;
        float* Bs = sm + STAGE_F;
        #pragma unroll
        for (int it = 0; it < 4; it++) {
            const int row = it * 32 + lr;
            float4 a4 = *(const float4*)&A[(size_t)(m0 + row) * GK + lc4];
            float4 b4 = *(const float4*)&B[(size_t)(n0 + row) * GK + lc4];
            *(float4*)&As[row * SM_STRIDE + lc4] = to_tf32x4(a4);
            *(float4*)&Bs[row * SM_STRIDE + lc4] = to_tf32x4(b4);
        }
    }
    __syncthreads();

    int s = 0;
    for (int c = 0; c < NUM_CHUNKS; c++) {
        const bool more = (c + 1 < NUM_CHUNKS);
        float4 pa[4], pb[4];
        if (more) {
            const int kc = (c + 1) * BK;
            #pragma unroll
            for (int it = 0; it < 4; it++) {
                const int row = it * 32 + lr;
                pa[it] = *(const float4*)&A[(size_t)(m0 + row) * GK + kc + lc4];
                pb[it] = *(const float4*)&B[(size_t)(n0 + row) * GK + kc + lc4];
            }
        }

        {
            const uint32_t* Asu = (const uint32_t*)(sm + 2 * s * STAGE_F);
            const uint32_t* Bsu = Asu + STAGE_F;
            #pragma unroll
            for (int ks = 0; ks < 4; ks++) {
                const int k0 = ks * 8 + t;
                uint32_t af[2][4];
                #pragma unroll
                for (int mt = 0; mt < 2; mt++) {
                    const int rb = warpM + mt * 16 + g;
                    af[mt][0] = Asu[rb * SM_STRIDE + k0];
                    af[mt][1] = Asu[(rb + 8) * SM_STRIDE + k0];
                    af[mt][2] = Asu[rb * SM_STRIDE + k0 + 4];
                    af[mt][3] = Asu[(rb + 8) * SM_STRIDE + k0 + 4];
                }
                #pragma unroll
                for (int nt = 0; nt < 8; nt++) {
                    const int cb = warpN + nt * 8 + g;
                    const uint32_t b0 = Bsu[cb * SM_STRIDE + k0];
                    const uint32_t b1 = Bsu[cb * SM_STRIDE + k0 + 4];
                    mma_tf32(acc[0][nt], af[0], b0, b1);
                    mma_tf32(acc[1][nt], af[1], b0, b1);
                }
            }
        }

        if (more) {
            __syncthreads();
            float* As = sm + 2 * (s ^ 1) * STAGE_F;
            float* Bs = As + STAGE_F;
            #pragma unroll
            for (int it = 0; it < 4; it++) {
                const int row = it * 32 + lr;
                *(float4*)&As[row * SM_STRIDE + lc4] = to_tf32x4(pa[it]);
                *(float4*)&Bs[row * SM_STRIDE + lc4] = to_tf32x4(pb[it]);
            }
            __syncthreads();
            s ^= 1;
        }
    }

    #pragma unroll
    for (int mt = 0; mt < 2; mt++) {
        #pragma unroll
        for (int nt = 0; nt < 8; nt++) {
            const int row = m0 + warpM + mt * 16 + g;
            const int col = n0 + warpN + nt * 8 + 2 * t;
            float2 bb = *(const float2*)&bias[col];
            float2 v0 = {acc[mt][nt][0] + bb.x, acc[mt][nt][1] + bb.y};
            float2 v1 = {acc[mt][nt][2] + bb.x, acc[mt][nt][3] + bb.y};
            *(float2*)&C[(size_t)row * GN + col] = v0;
            *(float2*)&C[(size_t)(row + 8) * GN + col] = v1;
        }
    }
}

// batched q/k/v projection: blockIdx.z selects which GEMM
__global__ __launch_bounds__(256) void gemm3_tf32_kernel(
    const float* __restrict__ q, const float* __restrict__ k,
    const float* __restrict__ v,
    const float* __restrict__ Wq, const float* __restrict__ bq,
    const float* __restrict__ Wk, const float* __restrict__ bk,
    const float* __restrict__ Wv, const float* __restrict__ bv,
    float* __restrict__ qp, float* __restrict__ kp, float* __restrict__ vp)
{
    extern __shared__ float sm[];
    const float *A, *B, *bias; float* C;
    if (blockIdx.z == 0)      { A = q; B = Wq; bias = bq; C = qp; }
    else if (blockIdx.z == 1) { A = k; B = Wk; bias = bk; C = kp; }
    else                      { A = v; B = Wv; bias = bv; C = vp; }
    gemm_body(A, B, bias, C, sm);
}

__global__ __launch_bounds__(256) void gemm_tf32_kernel(
    const float* __restrict__ A, const float* __restrict__ B,
    const float* __restrict__ bias, float* __restrict__ C)
{
    extern __shared__ float sm[];
    gemm_body(A, B, bias, C, sm);
}

// ---------------------------------------------------------------------------
// Tensor-core flash attention, Bq=128, Bk=64.
// 8 warps as 4(M) x 2(N): warp strip = 32 query rows x 32 key cols.
// Next-block K/V prefetched to registers during PV compute.
// ---------------------------------------------------------------------------
#define BQ 128
#define AQ 68
#define SSW 66
#define ATTN_SMEM ((BQ * AQ + 2 * 64 * AQ + BQ * SSW + 3 * BQ) * 4)  // 104960 B

__global__ __launch_bounds__(256) void attn_kernel(
    const float* __restrict__ qp, const float* __restrict__ kp,
    const float* __restrict__ vp, float* __restrict__ ao,
    const int* __restrict__ key_length)
{
    extern __shared__ float sm[];
    float* Qs    = sm;                    // [BQ][AQ]
    float* Ks    = Qs + BQ * AQ;          // [key][AQ]
    float* Vs    = Ks + 64 * AQ;          // [d][AQ] (transposed)
    float* Ss    = Vs + 64 * AQ;          // [BQ][SSW]
    float* row_m = Ss + BQ * SSW;         // BQ
    float* row_l = row_m + BQ;            // BQ
    float* row_c = row_l + BQ;            // BQ

    const int tid  = threadIdx.x;
    const int wid  = tid >> 5;
    const int lane = tid & 31;
    const int g    = lane >> 2;
    const int t    = lane & 3;
    const int warpM = (wid & 3) * 32;     // 32-row query strip
    const int warpN = (wid >> 2) * 32;    // 32-col key strip

    const int q0 = blockIdx.x * BQ;
    const int h  = blockIdx.y;
    const int n  = blockIdx.z;
    const int kl = key_length[n];
    const float scale = 0.125f;   // 1/sqrt(64)

    // --- load Q (tf32-rounded): 128 rows, 2 threads/row ---
    {
        const int r  = tid >> 1;
        const int dq = (tid & 1) * 32;
        const float* src = &qp[((size_t)(q0 + r) * N_DIM + n) * C_DIM + h * DH + dq];
        #pragma unroll
        for (int u = 0; u < 32; u += 4)
            *(float4*)&Qs[r * AQ + dq + u] = to_tf32x4(*(const float4*)&src[u]);
    }
    if (tid < BQ) { row_m[tid] = -1e30f; row_l[tid] = 0.0f; }

    const int kr  = tid >> 2;             // 0..63 (K/V row)
    const int kdq = (tid & 3) * 16;

    // block-inclusion predicate
    auto included = [&](int b) -> bool {
        const int k0 = b * 64;
        return (k0 < kl) ||
               (k0 <= q0 + BQ - 1 + WINDOW && k0 + 63 >= q0 - WINDOW);
    };

    // first included block: load K/V directly
    int kb = 0;
    while (kb < T_DIM / 64 && !included(kb)) kb++;
    if (kb < T_DIM / 64) {
        const float* ksrc = &kp[((size_t)(kb * 64 + kr) * N_DIM + n) * C_DIM + h * DH + kdq];
        const float* vsrc = &vp[((size_t)(kb * 64 + kr) * N_DIM + n) * C_DIM + h * DH + kdq];
        #pragma unroll
        for (int u = 0; u < 16; u += 4) {
            *(float4*)&Ks[kr * AQ + kdq + u] = to_tf32x4(*(const float4*)&ksrc[u]);
            float4 vv = to_tf32x4(*(const float4*)&vsrc[u]);
            Vs[(kdq + u + 0) * AQ + kr] = vv.x;
            Vs[(kdq + u + 1) * AQ + kr] = vv.y;
            Vs[(kdq + u + 2) * AQ + kr] = vv.z;
            Vs[(kdq + u + 3) * AQ + kr] = vv.w;
        }
    } else {
        kb = -1;
    }
    __syncthreads();

    float o[2][4][4] = {};   // [mt][nt][c-frag]

    while (kb >= 0) {
        const int k0b = kb * 64;
        // next included block
        int kbn = kb + 1;
        while (kbn < T_DIM / 64 && !included(kbn)) kbn++;
        if (kbn >= T_DIM / 64) kbn = -1;

        // --- S = Q K^T via mma ---
        float sf[2][4][4] = {};
        {
            const uint32_t* Qu = (const uint32_t*)Qs;
            const uint32_t* Ku = (const uint32_t*)Ks;
            #pragma unroll
            for (int ks = 0; ks < 8; ks++) {
                const int kk = ks * 8 + t;
                uint32_t a[2][4];
                #pragma unroll
                for (int mt = 0; mt < 2; mt++) {
                    const int rb = warpM + mt * 16 + g;
                    a[mt][0] = Qu[rb * AQ + kk];
                    a[mt][1] = Qu[(rb + 8) * AQ + kk];
                    a[mt][2] = Qu[rb * AQ + kk + 4];
                    a[mt][3] = Qu[(rb + 8) * AQ + kk + 4];
                }
                #pragma unroll
                for (int nt = 0; nt < 4; nt++) {
                    const int cb = warpN + nt * 8 + g;
                    const uint32_t b0 = Ku[cb * AQ + kk];
                    const uint32_t b1 = Ku[cb * AQ + kk + 4];
                    mma_tf32(sf[0][nt], a[0], b0, b1);
                    mma_tf32(sf[1][nt], a[1], b0, b1);
                }
            }
        }
        // mask + scale -> Ss
        #pragma unroll
        for (int mt = 0; mt < 2; mt++) {
            const int gi0 = q0 + warpM + mt * 16 + g;
            const int gi1 = gi0 + 8;
            #pragma unroll
            for (int nt = 0; nt < 4; nt++) {
                const int gj = k0b + warpN + nt * 8 + 2 * t;
                const bool m00 = (abs(gi0 - gj)     <= WINDOW) || (gj     < kl);
                const bool m01 = (abs(gi0 - gj - 1) <= WINDOW) || (gj + 1 < kl);
                const bool m10 = (abs(gi1 - gj)     <= WINDOW) || (gj     < kl);
                const bool m11 = (abs(gi1 - gj - 1) <= WINDOW) || (gj + 1 < kl);
                float2 v0 = { m00 ? sf[mt][nt][0] * scale : -1e9f,
                              m01 ? sf[mt][nt][1] * scale : -1e9f };
                float2 v1 = { m10 ? sf[mt][nt][2] * scale : -1e9f,
                              m11 ? sf[mt][nt][3] * scale : -1e9f };
                const int co = warpN + nt * 8 + 2 * t;
                *(float2*)&Ss[(warpM + mt * 16 + g)     * SSW + co] = v0;
                *(float2*)&Ss[(warpM + mt * 16 + 8 + g) * SSW + co] = v1;
            }
        }
        __syncthreads();

        // --- online softmax: 2 threads per row, 32 cols each ---
        {
            const int r  = tid >> 1;
            const int qd = tid & 1;
            float* srow = &Ss[r * SSW + qd * 32];
            float mx = -1e30f;
            #pragma unroll
            for (int c = 0; c < 32; c++) mx = fmaxf(mx, srow[c]);
            mx = fmaxf(mx, __shfl_xor_sync(0xffffffffu, mx, 1));
            const float m_old = row_m[r];
            const float m_new = fmaxf(m_old, mx);
            const float corr  = __expf(m_old - m_new);
            float sum = 0.0f;
            #pragma unroll
            for (int c = 0; c < 32; c++) {
                const float p = to_tf32(__expf(srow[c] - m_new));
                srow[c] = p;
                sum += p;
            }
            sum += __shfl_xor_sync(0xffffffffu, sum, 1);
            if (qd == 0) {
                row_l[r] = row_l[r] * corr + sum;
                row_m[r] = m_new;
                row_c[r] = corr;
            }
        }
        __syncthreads();

        // --- prefetch next K/V block into registers (latency hidden by PV) ---
        float4 pk[4], pv[4];
        if (kbn >= 0) {
            const float* ksrc = &kp[((size_t)(kbn * 64 + kr) * N_DIM + n) * C_DIM + h * DH + kdq];
            const float* vsrc = &vp[((size_t)(kbn * 64 + kr) * N_DIM + n) * C_DIM + h * DH + kdq];
            #pragma unroll
            for (int u = 0; u < 4; u++) {
                pk[u] = *(const float4*)&ksrc[u * 4];
                pv[u] = *(const float4*)&vsrc[u * 4];
            }
        }

        // --- O = O*corr + P V via mma ---
        {
            #pragma unroll
            for (int mt = 0; mt < 2; mt++) {
                const float c0 = row_c[warpM + mt * 16 + g];
                const float c1 = row_c[warpM + mt * 16 + 8 + g];
                #pragma unroll
                for (int nt = 0; nt < 4; nt++) {
                    o[mt][nt][0] *= c0; o[mt][nt][1] *= c0;
                    o[mt][nt][2] *= c1; o[mt][nt][3] *= c1;
                }
            }
            const uint32_t* Pu = (const uint32_t*)Ss;
            const uint32_t* Vu = (const uint32_t*)Vs;
            #pragma unroll
            for (int ks = 0; ks < 8; ks++) {
                const int kk = ks * 8 + t;
                uint32_t a[2][4];
                #pragma unroll
                for (int mt = 0; mt < 2; mt++) {
                    const int rb = warpM + mt * 16 + g;
                    a[mt][0] = Pu[rb * SSW + kk];
                    a[mt][1] = Pu[(rb + 8) * SSW + kk];
                    a[mt][2] = Pu[rb * SSW + kk + 4];
                    a[mt][3] = Pu[(rb + 8) * SSW + kk + 4];
                }
                #pragma unroll
                for (int nt = 0; nt < 4; nt++) {
                    const int cb = warpN + nt * 8 + g;
                    const uint32_t b0 = Vu[cb * AQ + kk];
                    const uint32_t b1 = Vu[cb * AQ + kk + 4];
                    mma_tf32(o[0][nt], a[0], b0, b1);
                    mma_tf32(o[1][nt], a[1], b0, b1);
                }
            }
        }
        __syncthreads();   // PV done reading Ks/Vs/Ss

        if (kbn >= 0) {
            #pragma unroll
            for (int u = 0; u < 4; u++) {
                *(float4*)&Ks[kr * AQ + kdq + u * 4] = to_tf32x4(pk[u]);
                float4 vv = to_tf32x4(pv[u]);
                Vs[(kdq + u * 4 + 0) * AQ + kr] = vv.x;
                Vs[(kdq + u * 4 + 1) * AQ + kr] = vv.y;
                Vs[(kdq + u * 4 + 2) * AQ + kr] = vv.z;
                Vs[(kdq + u * 4 + 3) * AQ + kr] = vv.w;
            }
            __syncthreads();  // Ks/Vs ready for next QK
        }
        kb = kbn;
    }

    // --- normalize + write out ---
    #pragma unroll
    for (int mt = 0; mt < 2; mt++) {
        const float i0 = 1.0f / row_l[warpM + mt * 16 + g];
        const float i1 = 1.0f / row_l[warpM + mt * 16 + 8 + g];
        const int row0 = q0 + warpM + mt * 16 + g;
        #pragma unroll
        for (int nt = 0; nt < 4; nt++) {
            const int col = h * DH + warpN + nt * 8 + 2 * t;
            float2 w0 = { o[mt][nt][0] * i0, o[mt][nt][1] * i0 };
            float2 w1 = { o[mt][nt][2] * i1, o[mt][nt][3] * i1 };
            *(float2*)&ao[((size_t)row0 * N_DIM + n) * C_DIM + col] = w0;
            *(float2*)&ao[((size_t)(row0 + 8) * N_DIM + n) * C_DIM + col] = w1;
        }
    }
}

// ---------------------------------------------------------------------------
extern "C" void kernel_launch(void* const* d_in, const int* in_sizes, int n_in,
                              void* d_out, int out_size)
{
    (void)in_sizes; (void)n_in; (void)out_size;
    const float* q  = (const float*)d_in[0];
    const float* k  = (const float*)d_in[1];
    const float* v  = (const float*)d_in[2];
    const float* Wq = (const float*)d_in[3];
    const float* bq = (const float*)d_in[4];
    const float* Wk = (const float*)d_in[5];
    const float* bk = (const float*)d_in[6];
    const float* Wv = (const float*)d_in[7];
    const float* bv = (const float*)d_in[8];
    const float* Wo = (const float*)d_in[9];
    const float* bo = (const float*)d_in[10];
    const int* key_length = (const int*)d_in[11];
    float* out = (float*)d_out;

    float *qp, *kp, *vp, *aop;
    cudaGetSymbolAddress((void**)&qp,  g_qp);
    cudaGetSymbolAddress((void**)&kp,  g_kp);
    cudaGetSymbolAddress((void**)&vp,  g_vp);
    cudaGetSymbolAddress((void**)&aop, g_ao);

    cudaFuncSetAttribute(gemm3_tf32_kernel,
                         cudaFuncAttributeMaxDynamicSharedMemorySize, GEMM_SMEM);
    cudaFuncSetAttribute(gemm_tf32_kernel,
                         cudaFuncAttributeMaxDynamicSharedMemorySize, GEMM_SMEM);

    // batched q/k/v projections (one launch, 768 CTAs)
    gemm3_tf32_kernel<<<dim3(GN / 128, M_ROWS / 128, 3), 256, GEMM_SMEM>>>(
        q, k, v, Wq, bq, Wk, bk, Wv, bv, qp, kp, vp);

    // attention (tensor-core, Bq=128, K/V prefetch)
    cudaFuncSetAttribute(attn_kernel,
                         cudaFuncAttributeMaxDynamicSharedMemorySize, ATTN_SMEM);
    attn_kernel<<<dim3(T_DIM / BQ, H_DIM, N_DIM), 256, ATTN_SMEM>>>(
        qp, kp, vp, aop, key_length);

    // output projection
    gemm_tf32_kernel<<<dim3(GN / 128, M_ROWS / 128), 256, GEMM_SMEM>>>(
        aop, Wo, bo, out);
}

// round 10
// speedup vs baseline: 1.0797x; 1.0797x over previous
#include <cuda_runtime.h>
#include <math.h>
#include <stdint.h>

#define T_DIM 2048
#define N_DIM 2
#define C_DIM 1024
#define H_DIM 16
#define DH 64
#define M_ROWS (T_DIM * N_DIM)   // 4096
#define WINDOW 128

#define GK 1024
#define GN 1024
#define BK 32
#define NUM_CHUNKS (GK / BK)     // 32
#define SM_STRIDE 36             // 32 + 4 pad (floats)
#define STAGE_F (128 * SM_STRIDE)            // floats per matrix tile
#define GEMM_SMEM (2 * 2 * STAGE_F * 4)      // 2 stages x (A+B) = 73728 B

// Scratch (static device allocation — allowed; cudaMalloc is not)
__device__ float g_qp[M_ROWS * C_DIM];
__device__ float g_kp[M_ROWS * C_DIM];
__device__ float g_vp[M_ROWS * C_DIM];
__device__ float g_ao[M_ROWS * C_DIM];

// ---------------------------------------------------------------------------
__device__ __forceinline__ float to_tf32(float x) {
    float y;
    asm("cvt.rna.tf32.f32 %0, %1;" : "=f"(y) : "f"(x));
    return y;
}
__device__ __forceinline__ float4 to_tf32x4(float4 v) {
    return make_float4(to_tf32(v.x), to_tf32(v.y), to_tf32(v.z), to_tf32(v.w));
}

__device__ __forceinline__ void mma_tf32(float* c, const uint32_t* a,
                                         uint32_t b0, uint32_t b1) {
    asm volatile(
        "mma.sync.aligned.m16n8k8.row.col.f32.tf32.tf32.f32 "
        "{%0,%1,%2,%3}, {%4,%5,%6,%7}, {%8,%9}, {%0,%1,%2,%3};"
        : "+f"(c[0]), "+f"(c[1]), "+f"(c[2]), "+f"(c[3])
        : "r"(a[0]), "r"(a[1]), "r"(a[2]), "r"(a[3]), "r"(b0), "r"(b1));
}

// ---------------------------------------------------------------------------
// mma.sync tf32 GEMM body: C[m][n] = sum_k A[m][k]*B[n][k] + bias[n]
// CTA tile 128x128, BK=32, 8 warps (4m x 2n), warp tile 32x64.
// One barrier per chunk: compute(s) -> LDG+cvt+STS(s^1) -> bar.
// (STS(s^1) is safe without a pre-barrier: its last readers were compute(c-1),
//  which everyone finished before the barrier at the end of c-1.)
// ---------------------------------------------------------------------------
__device__ __forceinline__ void gemm_body(
    const float* __restrict__ A, const float* __restrict__ B,
    const float* __restrict__ bias, float* __restrict__ C, float* sm)
{
    const int tid  = threadIdx.x;
    const int wid  = tid >> 5;
    const int lane = tid & 31;
    const int g    = lane >> 2;
    const int t    = lane & 3;
    const int warpM = (wid & 3) * 32;
    const int warpN = (wid >> 2) * 64;
    const int m0 = blockIdx.y * 128;
    const int n0 = blockIdx.x * 128;

    const int lr  = tid >> 3;
    const int lc4 = (tid & 7) * 4;

    float acc[2][8][4] = {};

    // --- load chunk 0 into stage 0 ---
    {
        float* As = sm;
        float* Bs = sm + STAGE_F;
        #pragma unroll
        for (int it = 0; it < 4; it++) {
            const int row = it * 32 + lr;
            float4 a4 = *(const float4*)&A[(size_t)(m0 + row) * GK + lc4];
            float4 b4 = *(const float4*)&B[(size_t)(n0 + row) * GK + lc4];
            *(float4*)&As[row * SM_STRIDE + lc4] = to_tf32x4(a4);
            *(float4*)&Bs[row * SM_STRIDE + lc4] = to_tf32x4(b4);
        }
    }
    __syncthreads();

    int s = 0;
    for (int c = 0; c < NUM_CHUNKS; c++) {
        // --- compute on stage s ---
        {
            const uint32_t* Asu = (const uint32_t*)(sm + 2 * s * STAGE_F);
            const uint32_t* Bsu = Asu + STAGE_F;
            #pragma unroll
            for (int ks = 0; ks < 4; ks++) {
                const int k0 = ks * 8 + t;
                uint32_t af[2][4];
                #pragma unroll
                for (int mt = 0; mt < 2; mt++) {
                    const int rb = warpM + mt * 16 + g;
                    af[mt][0] = Asu[rb * SM_STRIDE + k0];
                    af[mt][1] = Asu[(rb + 8) * SM_STRIDE + k0];
                    af[mt][2] = Asu[rb * SM_STRIDE + k0 + 4];
                    af[mt][3] = Asu[(rb + 8) * SM_STRIDE + k0 + 4];
                }
                #pragma unroll
                for (int nt = 0; nt < 8; nt++) {
                    const int cb = warpN + nt * 8 + g;
                    const uint32_t b0 = Bsu[cb * SM_STRIDE + k0];
                    const uint32_t b1 = Bsu[cb * SM_STRIDE + k0 + 4];
                    mma_tf32(acc[0][nt], af[0], b0, b1);
                    mma_tf32(acc[1][nt], af[1], b0, b1);
                }
            }
        }

        // --- stream next chunk into stage s^1 ---
        if (c + 1 < NUM_CHUNKS) {
            const int kc = (c + 1) * BK;
            float* As = sm + 2 * (s ^ 1) * STAGE_F;
            float* Bs = As + STAGE_F;
            #pragma unroll
            for (int it = 0; it < 4; it++) {
                const int row = it * 32 + lr;
                float4 a4 = *(const float4*)&A[(size_t)(m0 + row) * GK + kc + lc4];
                float4 b4 = *(const float4*)&B[(size_t)(n0 + row) * GK + kc + lc4];
                *(float4*)&As[row * SM_STRIDE + lc4] = to_tf32x4(a4);
                *(float4*)&Bs[row * SM_STRIDE + lc4] = to_tf32x4(b4);
            }
        }
        __syncthreads();
        s ^= 1;
    }

    // --- epilogue: bias + store ---
    #pragma unroll
    for (int mt = 0; mt < 2; mt++) {
        #pragma unroll
        for (int nt = 0; nt < 8; nt++) {
            const int row = m0 + warpM + mt * 16 + g;
            const int col = n0 + warpN + nt * 8 + 2 * t;
            float2 bb = *(const float2*)&bias[col];
            float2 v0 = {acc[mt][nt][0] + bb.x, acc[mt][nt][1] + bb.y};
            float2 v1 = {acc[mt][nt][2] + bb.x, acc[mt][nt][3] + bb.y};
            *(float2*)&C[(size_t)row * GN + col] = v0;
            *(float2*)&C[(size_t)(row + 8) * GN + col] = v1;
        }
    }
}

// batched q/k/v projection: blockIdx.z selects which GEMM
__global__ __launch_bounds__(256, 2) void gemm3_tf32_kernel(
    const float* __restrict__ q, const float* __restrict__ k,
    const float* __restrict__ v,
    const float* __restrict__ Wq, const float* __restrict__ bq,
    const float* __restrict__ Wk, const float* __restrict__ bk,
    const float* __restrict__ Wv, const float* __restrict__ bv,
    float* __restrict__ qp, float* __restrict__ kp, float* __restrict__ vp)
{
    extern __shared__ float sm[];
    const float *A, *B, *bias; float* C;
    if (blockIdx.z == 0)      { A = q; B = Wq; bias = bq; C = qp; }
    else if (blockIdx.z == 1) { A = k; B = Wk; bias = bk; C = kp; }
    else                      { A = v; B = Wv; bias = bv; C = vp; }
    gemm_body(A, B, bias, C, sm);
}

__global__ __launch_bounds__(256, 2) void gemm_tf32_kernel(
    const float* __restrict__ A, const float* __restrict__ B,
    const float* __restrict__ bias, float* __restrict__ C)
{
    extern __shared__ float sm[];
    gemm_body(A, B, bias, C, sm);
}

// ---------------------------------------------------------------------------
// Tensor-core flash attention, Bq=128, Bk=64.
// 8 warps as 4(M) x 2(N): warp strip = 32 query rows x 32 key cols.
// No register prefetch — occupancy (2 CTAs/SM) provides the overlap.
// ---------------------------------------------------------------------------
#define BQ 128
#define AQ 68
#define SSW 66
#define ATTN_SMEM ((BQ * AQ + 2 * 64 * AQ + BQ * SSW + 3 * BQ) * 4)  // 104960 B

__global__ __launch_bounds__(256, 2) void attn_kernel(
    const float* __restrict__ qp, const float* __restrict__ kp,
    const float* __restrict__ vp, float* __restrict__ ao,
    const int* __restrict__ key_length)
{
    extern __shared__ float sm[];
    float* Qs    = sm;                    // [BQ][AQ]
    float* Ks    = Qs + BQ * AQ;          // [key][AQ]
    float* Vs    = Ks + 64 * AQ;          // [d][AQ] (transposed)
    float* Ss    = Vs + 64 * AQ;          // [BQ][SSW]
    float* row_m = Ss + BQ * SSW;         // BQ
    float* row_l = row_m + BQ;            // BQ
    float* row_c = row_l + BQ;            // BQ

    const int tid  = threadIdx.x;
    const int wid  = tid >> 5;
    const int lane = tid & 31;
    const int g    = lane >> 2;
    const int t    = lane & 3;
    const int warpM = (wid & 3) * 32;     // 32-row query strip
    const int warpN = (wid >> 2) * 32;    // 32-col key strip

    const int q0 = blockIdx.x * BQ;
    const int h  = blockIdx.y;
    const int n  = blockIdx.z;
    const int kl = key_length[n];
    const float scale = 0.125f;   // 1/sqrt(64)

    // --- load Q (tf32-rounded): 128 rows, 2 threads/row ---
    {
        const int r  = tid >> 1;
        const int dq = (tid & 1) * 32;
        const float* src = &qp[((size_t)(q0 + r) * N_DIM + n) * C_DIM + h * DH + dq];
        #pragma unroll
        for (int u = 0; u < 32; u += 4)
            *(float4*)&Qs[r * AQ + dq + u] = to_tf32x4(*(const float4*)&src[u]);
    }
    if (tid < BQ) { row_m[tid] = -1e30f; row_l[tid] = 0.0f; }

    const int kr  = tid >> 2;             // 0..63 (K/V row)
    const int kdq = (tid & 3) * 16;

    auto included = [&](int b) -> bool {
        const int k0 = b * 64;
        return (k0 < kl) ||
               (k0 <= q0 + BQ - 1 + WINDOW && k0 + 63 >= q0 - WINDOW);
    };
    auto load_kv = [&](int b) {
        const float* ksrc = &kp[((size_t)(b * 64 + kr) * N_DIM + n) * C_DIM + h * DH + kdq];
        const float* vsrc = &vp[((size_t)(b * 64 + kr) * N_DIM + n) * C_DIM + h * DH + kdq];
        #pragma unroll
        for (int u = 0; u < 16; u += 4) {
            *(float4*)&Ks[kr * AQ + kdq + u] = to_tf32x4(*(const float4*)&ksrc[u]);
            float4 vv = to_tf32x4(*(const float4*)&vsrc[u]);
            Vs[(kdq + u + 0) * AQ + kr] = vv.x;
            Vs[(kdq + u + 1) * AQ + kr] = vv.y;
            Vs[(kdq + u + 2) * AQ + kr] = vv.z;
            Vs[(kdq + u + 3) * AQ + kr] = vv.w;
        }
    };

    // first included block
    int kb = 0;
    while (kb < T_DIM / 64 && !included(kb)) kb++;
    if (kb < T_DIM / 64) load_kv(kb); else kb = -1;
    __syncthreads();

    float o[2][4][4] = {};   // [mt][nt][c-frag]

    while (kb >= 0) {
        const int k0b = kb * 64;
        int kbn = kb + 1;
        while (kbn < T_DIM / 64 && !included(kbn)) kbn++;
        if (kbn >= T_DIM / 64) kbn = -1;

        // --- S = Q K^T via mma ---
        float sf[2][4][4] = {};
        {
            const uint32_t* Qu = (const uint32_t*)Qs;
            const uint32_t* Ku = (const uint32_t*)Ks;
            #pragma unroll
            for (int ks = 0; ks < 8; ks++) {
                const int kk = ks * 8 + t;
                uint32_t a[2][4];
                #pragma unroll
                for (int mt = 0; mt < 2; mt++) {
                    const int rb = warpM + mt * 16 + g;
                    a[mt][0] = Qu[rb * AQ + kk];
                    a[mt][1] = Qu[(rb + 8) * AQ + kk];
                    a[mt][2] = Qu[rb * AQ + kk + 4];
                    a[mt][3] = Qu[(rb + 8) * AQ + kk + 4];
                }
                #pragma unroll
                for (int nt = 0; nt < 4; nt++) {
                    const int cb = warpN + nt * 8 + g;
                    const uint32_t b0 = Ku[cb * AQ + kk];
                    const uint32_t b1 = Ku[cb * AQ + kk + 4];
                    mma_tf32(sf[0][nt], a[0], b0, b1);
                    mma_tf32(sf[1][nt], a[1], b0, b1);
                }
            }
        }
        // mask + scale -> Ss
        #pragma unroll
        for (int mt = 0; mt < 2; mt++) {
            const int gi0 = q0 + warpM + mt * 16 + g;
            const int gi1 = gi0 + 8;
            #pragma unroll
            for (int nt = 0; nt < 4; nt++) {
                const int gj = k0b + warpN + nt * 8 + 2 * t;
                const bool m00 = (abs(gi0 - gj)     <= WINDOW) || (gj     < kl);
                const bool m01 = (abs(gi0 - gj - 1) <= WINDOW) || (gj + 1 < kl);
                const bool m10 = (abs(gi1 - gj)     <= WINDOW) || (gj     < kl);
                const bool m11 = (abs(gi1 - gj - 1) <= WINDOW) || (gj + 1 < kl);
                float2 v0 = { m00 ? sf[mt][nt][0] * scale : -1e9f,
                              m01 ? sf[mt][nt][1] * scale : -1e9f };
                float2 v1 = { m10 ? sf[mt][nt][2] * scale : -1e9f,
                              m11 ? sf[mt][nt][3] * scale : -1e9f };
                const int co = warpN + nt * 8 + 2 * t;
                *(float2*)&Ss[(warpM + mt * 16 + g)     * SSW + co] = v0;
                *(float2*)&Ss[(warpM + mt * 16 + 8 + g) * SSW + co] = v1;
            }
        }
        __syncthreads();

        // --- online softmax: 2 threads per row, 32 cols each ---
        {
            const int r  = tid >> 1;
            const int qd = tid & 1;
            float* srow = &Ss[r * SSW + qd * 32];
            float mx = -1e30f;
            #pragma unroll
            for (int c = 0; c < 32; c++) mx = fmaxf(mx, srow[c]);
            mx = fmaxf(mx, __shfl_xor_sync(0xffffffffu, mx, 1));
            const float m_old = row_m[r];
            const float m_new = fmaxf(m_old, mx);
            const float corr  = __expf(m_old - m_new);
            float sum = 0.0f;
            #pragma unroll
            for (int c = 0; c < 32; c++) {
                const float p = to_tf32(__expf(srow[c] - m_new));
                srow[c] = p;
                sum += p;
            }
            sum += __shfl_xor_sync(0xffffffffu, sum, 1);
            if (qd == 0) {
                row_l[r] = row_l[r] * corr + sum;
                row_m[r] = m_new;
                row_c[r] = corr;
            }
        }
        __syncthreads();

        // --- O = O*corr + P V via mma ---
        {
            #pragma unroll
            for (int mt = 0; mt < 2; mt++) {
                const float c0 = row_c[warpM + mt * 16 + g];
                const float c1 = row_c[warpM + mt * 16 + 8 + g];
                #pragma unroll
                for (int nt = 0; nt < 4; nt++) {
                    o[mt][nt][0] *= c0; o[mt][nt][1] *= c0;
                    o[mt][nt][2] *= c1; o[mt][nt][3] *= c1;
                }
            }
            const uint32_t* Pu = (const uint32_t*)Ss;
            const uint32_t* Vu = (const uint32_t*)Vs;
            #pragma unroll
            for (int ks = 0; ks < 8; ks++) {
                const int kk = ks * 8 + t;
                uint32_t a[2][4];
                #pragma unroll
                for (int mt = 0; mt < 2; mt++) {
                    const int rb = warpM + mt * 16 + g;
                    a[mt][0] = Pu[rb * SSW + kk];
                    a[mt][1] = Pu[(rb + 8) * SSW + kk];
                    a[mt][2] = Pu[rb * SSW + kk + 4];
                    a[mt][3] = Pu[(rb + 8) * SSW + kk + 4];
                }
                #pragma unroll
                for (int nt = 0; nt < 4; nt++) {
                    const int cb = warpN + nt * 8 + g;
                    const uint32_t b0 = Vu[cb * AQ + kk];
                    const uint32_t b1 = Vu[cb * AQ + kk + 4];
                    mma_tf32(o[0][nt], a[0], b0, b1);
                    mma_tf32(o[1][nt], a[1], b0, b1);
                }
            }
        }
        __syncthreads();   // PV done reading Ks/Vs/Ss

        if (kbn >= 0) {
            load_kv(kbn);
            __syncthreads();  // Ks/Vs ready for next QK
        }
        kb = kbn;
    }

    // --- normalize + write out ---
    #pragma unroll
    for (int mt = 0; mt < 2; mt++) {
        const float i0 = 1.0f / row_l[warpM + mt * 16 + g];
        const float i1 = 1.0f / row_l[warpM + mt * 16 + 8 + g];
        const int row0 = q0 + warpM + mt * 16 + g;
        #pragma unroll
        for (int nt = 0; nt < 4; nt++) {
            const int col = h * DH + warpN + nt * 8 + 2 * t;
            float2 w0 = { o[mt][nt][0] * i0, o[mt][nt][1] * i0 };
            float2 w1 = { o[mt][nt][2] * i1, o[mt][nt][3] * i1 };
            *(float2*)&ao[((size_t)row0 * N_DIM + n) * C_DIM + col] = w0;
            *(float2*)&ao[((size_t)(row0 + 8) * N_DIM + n) * C_DIM + col] = w1;
        }
    }
}

// ---------------------------------------------------------------------------
extern "C" void kernel_launch(void* const* d_in, const int* in_sizes, int n_in,
                              void* d_out, int out_size)
{
    (void)in_sizes; (void)n_in; (void)out_size;
    const float* q  = (const float*)d_in[0];
    const float* k  = (const float*)d_in[1];
    const float* v  = (const float*)d_in[2];
    const float* Wq = (const float*)d_in[3];
    const float* bq = (const float*)d_in[4];
    const float* Wk = (const float*)d_in[5];
    const float* bk = (const float*)d_in[6];
    const float* Wv = (const float*)d_in[7];
    const float* bv = (const float*)d_in[8];
    const float* Wo = (const float*)d_in[9];
    const float* bo = (const float*)d_in[10];
    const int* key_length = (const int*)d_in[11];
    float* out = (float*)d_out;

    float *qp, *kp, *vp, *aop;
    cudaGetSymbolAddress((void**)&qp,  g_qp);
    cudaGetSymbolAddress((void**)&kp,  g_kp);
    cudaGetSymbolAddress((void**)&vp,  g_vp);
    cudaGetSymbolAddress((void**)&aop, g_ao);

    cudaFuncSetAttribute(gemm3_tf32_kernel,
                         cudaFuncAttributeMaxDynamicSharedMemorySize, GEMM_SMEM);
    cudaFuncSetAttribute(gemm_tf32_kernel,
                         cudaFuncAttributeMaxDynamicSharedMemorySize, GEMM_SMEM);

    // batched q/k/v projections (one launch, 768 CTAs)
    gemm3_tf32_kernel<<<dim3(GN / 128, M_ROWS / 128, 3), 256, GEMM_SMEM>>>(
        q, k, v, Wq, bq, Wk, bk, Wv, bv, qp, kp, vp);

    // attention (tensor-core, Bq=128)
    cudaFuncSetAttribute(attn_kernel,
                         cudaFuncAttributeMaxDynamicSharedMemorySize, ATTN_SMEM);
    attn_kernel<<<dim3(T_DIM / BQ, H_DIM, N_DIM), 256, ATTN_SMEM>>>(
        qp, kp, vp, aop, key_length);

    // output projection
    gemm_tf32_kernel<<<dim3(GN / 128, M_ROWS / 128), 256, GEMM_SMEM>>>(
        aop, Wo, bo, out);
}